// round 10
// baseline (speedup 1.0000x reference)
#include <cuda_runtime.h>
#include <cuda_bf16.h>
#include <math.h>
#include <stdint.h>

// ---------------------------------------------------------------------------
// MambaBottleneck: B=8, L=4096, D_MODEL=256, D_INNER=512, D_STATE=16,
// DT_RANK=16, D_CONV=4.  M = B*L = 32768 rows.
// ---------------------------------------------------------------------------

#define BATCH   8
#define SEQLEN  4096
#define DMODEL  256
#define DINNER  512
#define DSTATE  16
#define MROWS   (BATCH * SEQLEN)          // 32768
#define NCH     (BATCH * DINNER)          // 4096

// scratch layout (float units; bf16 arrays use half-sized float counts)
#define OFF_XZ      0
#define SZ_XZ       (MROWS * 1024)
#define OFF_UC      (OFF_XZ + SZ_XZ)
#define SZ_UC       (MROWS * DINNER)
#define OFF_UCT     (OFF_UC + SZ_UC)
#define SZ_UCT      (NCH * SEQLEN)
#define OFF_XDBL    (OFF_UCT + SZ_UCT)
#define SZ_XDBL     (MROWS * 48)
#define OFF_DELTAT  (OFF_XDBL + SZ_XDBL)
#define SZ_DELTAT   (NCH * SEQLEN)
#define OFF_YSCANT  (OFF_DELTAT + SZ_DELTAT)
#define SZ_YSCANT   (NCH * SEQLEN)
#define OFF_OUTTMP  (OFF_YSCANT + SZ_YSCANT)
#define SZ_OUTTMP   (MROWS * DMODEL)
#define OFF_XH      (OFF_OUTTMP + SZ_OUTTMP)
#define SZ_XH       (MROWS * DMODEL / 2)
#define OFF_XL      (OFF_XH + SZ_XH)
#define OFF_YH      (OFF_XL + SZ_XH)
#define SZ_YH       (MROWS * DINNER / 2)
#define OFF_YL      (OFF_YH + SZ_YH)
#define OFF_WIH     (OFF_YL + SZ_YH)
#define SZ_WIH      (1024 * DMODEL / 2)
#define OFF_WIL     (OFF_WIH + SZ_WIH)
#define OFF_WOH     (OFF_WIL + SZ_WIH)
#define SZ_WOH      (DMODEL * DINNER / 2)
#define OFF_WOL     (OFF_WOH + SZ_WOH)
#define SCRATCH_TOTAL (OFF_WOL + SZ_WOH)

static __device__ float g_scratch[SCRATCH_TOTAL];

// ---------------------------------------------------------------------------
// fp32 -> bf16 hi/lo split (vectorized float4 -> 2x uint2)
// ---------------------------------------------------------------------------
__global__ __launch_bounds__(256) void split_kernel(
    const float4* __restrict__ src, uint2* __restrict__ h,
    uint2* __restrict__ l, int n4)
{
    const int i = blockIdx.x * blockDim.x + threadIdx.x;
    if (i >= n4) return;
    const float4 v = src[i];
    __nv_bfloat162 h0, h1, l0, l1;
    h0.x = __float2bfloat16(v.x); h0.y = __float2bfloat16(v.y);
    h1.x = __float2bfloat16(v.z); h1.y = __float2bfloat16(v.w);
    l0.x = __float2bfloat16(v.x - __bfloat162float(h0.x));
    l0.y = __float2bfloat16(v.y - __bfloat162float(h0.y));
    l1.x = __float2bfloat16(v.z - __bfloat162float(h1.x));
    l1.y = __float2bfloat16(v.w - __bfloat162float(h1.y));
    h[i] = make_uint2(*(uint32_t*)&h0, *(uint32_t*)&h1);
    l[i] = make_uint2(*(uint32_t*)&l0, *(uint32_t*)&l1);
}

// ---------------------------------------------------------------------------
// Tensor-core GEMM, pre-split bf16, cp.async double-buffered, STATIC 48KB smem.
// C = A @ W^T, acc = Ah*Wh + Ah*Wl + Al*Wh. Block tile 128x128x16, 8 warps
// (4m x 2n), warp tile 32x64. Smem rows stride 12 words (conflict-free:
// g*12 mod 32 = {0,12,24,4,16,28,8,20}). __launch_bounds__(256,2).
// ---------------------------------------------------------------------------
__device__ __forceinline__ void mma_bf16(float* c, const uint32_t* a,
                                         uint32_t b0, uint32_t b1)
{
    asm volatile(
        "mma.sync.aligned.m16n8k16.row.col.f32.bf16.bf16.f32 "
        "{%0,%1,%2,%3}, {%4,%5,%6,%7}, {%8,%9}, {%0,%1,%2,%3};"
        : "+f"(c[0]), "+f"(c[1]), "+f"(c[2]), "+f"(c[3])
        : "r"(a[0]), "r"(a[1]), "r"(a[2]), "r"(a[3]), "r"(b0), "r"(b1));
}

__device__ __forceinline__ void cp16(uint32_t smem_addr, const void* gptr)
{
    asm volatile("cp.async.ca.shared.global [%0], [%1], 16;"
                 :: "r"(smem_addr), "l"(gptr));
}

#define SPAD 12   // 8 data words (16 bf16) + 4 pad

__global__ __launch_bounds__(256, 2) void gemm_tc4_kernel(
    const __nv_bfloat16* __restrict__ Ah_, const __nv_bfloat16* __restrict__ Al_,
    const __nv_bfloat16* __restrict__ Wh_, const __nv_bfloat16* __restrict__ Wl_,
    float* __restrict__ C, int M, int N, int K)
{
    __shared__ uint32_t smem[2][4][128][SPAD];   // 49152 bytes (static)

    const int bm = blockIdx.y * 128;
    const int bn = blockIdx.x * 128;
    const int tid = threadIdx.x;
    const int lane = tid & 31;
    const int g   = lane >> 2;     // 0..7
    const int tig = lane & 3;      // 0..3
    const int w   = tid >> 5;
    const int wm  = (w >> 1) * 32; // 4 warps along m
    const int wn  = (w & 1) * 64;  // 2 warps along n

    // copy assignment: thread t -> row = t>>1, 16B chunk = (t&1)
    const int crow  = tid >> 1;          // 0..127
    const int chalf = tid & 1;           // 0 or 1
    const int ccol  = chalf * 8;         // bf16 element offset
    const int cword = chalf * 4;         // smem word offset

    const __nv_bfloat16* gp[4];
    gp[0] = Ah_ + (size_t)(bm + crow) * K + ccol;
    gp[1] = Al_ + (size_t)(bm + crow) * K + ccol;
    gp[2] = Wh_ + (size_t)(bn + crow) * K + ccol;
    gp[3] = Wl_ + (size_t)(bn + crow) * K + ccol;

    uint32_t sdst[4];
#pragma unroll
    for (int a = 0; a < 4; a++)
        sdst[a] = (uint32_t)__cvta_generic_to_shared(&smem[0][a][crow][cword]);
    const uint32_t stStride = 4 * 128 * SPAD * 4;   // bytes per stage

    float acc[2][8][4];
#pragma unroll
    for (int i = 0; i < 2; i++)
#pragma unroll
        for (int j = 0; j < 8; j++)
#pragma unroll
            for (int q = 0; q < 4; q++) acc[i][j][q] = 0.f;

    const int KT = K >> 4;   // k-tiles of 16

    // issue k-tile kt into stage st
    auto issue = [&](int kt, int st) {
        const int o = kt * 16;
        const uint32_t sb = (uint32_t)st * stStride;
#pragma unroll
        for (int a = 0; a < 4; a++)
            cp16(sdst[a] + sb, gp[a] + o);
    };

    issue(0, 0);
    asm volatile("cp.async.commit_group;");

    for (int kt = 0; kt < KT; kt++) {
        const int st = kt & 1;
        if (kt + 1 < KT) {
            issue(kt + 1, st ^ 1);
            asm volatile("cp.async.commit_group;");
            asm volatile("cp.async.wait_group 1;");
        } else {
            asm volatile("cp.async.wait_group 0;");
        }
        __syncthreads();

        // fragment loads + mma (one k16 step)
        uint32_t ah[2][4], al[2][4];
#pragma unroll
        for (int im = 0; im < 2; im++) {
            const int r = wm + im * 16 + g;
            ah[im][0] = smem[st][0][r][tig];         al[im][0] = smem[st][1][r][tig];
            ah[im][1] = smem[st][0][r + 8][tig];     al[im][1] = smem[st][1][r + 8][tig];
            ah[im][2] = smem[st][0][r][tig + 4];     al[im][2] = smem[st][1][r][tig + 4];
            ah[im][3] = smem[st][0][r + 8][tig + 4]; al[im][3] = smem[st][1][r + 8][tig + 4];
        }
#pragma unroll
        for (int jn = 0; jn < 8; jn++) {
            const int nr = wn + jn * 8 + g;
            const uint32_t bh0 = smem[st][2][nr][tig], bh1 = smem[st][2][nr][tig + 4];
            const uint32_t bl0 = smem[st][3][nr][tig], bl1 = smem[st][3][nr][tig + 4];
#pragma unroll
            for (int im = 0; im < 2; im++) {
                mma_bf16(acc[im][jn], ah[im], bh0, bh1);  // hi*hi
                mma_bf16(acc[im][jn], ah[im], bl0, bl1);  // hi*lo
                mma_bf16(acc[im][jn], al[im], bh0, bh1);  // lo*hi
            }
        }
        __syncthreads();
    }

#pragma unroll
    for (int im = 0; im < 2; im++) {
        const int row = bm + wm + im * 16 + g;
#pragma unroll
        for (int jn = 0; jn < 8; jn++) {
            const int col = bn + wn + jn * 8 + 2 * tig;
            float2 v0 = make_float2(acc[im][jn][0], acc[im][jn][1]);
            float2 v1 = make_float2(acc[im][jn][2], acc[im][jn][3]);
            *(float2*)(C + (size_t)row * N + col)       = v0;
            *(float2*)(C + (size_t)(row + 8) * N + col) = v1;
        }
    }
}

// ---------------------------------------------------------------------------
// SGEMM 128x64x16 (for x_proj, N=48 with guard).
// ---------------------------------------------------------------------------
__global__ __launch_bounds__(256) void sgemm_kernel(
    const float* __restrict__ A, const float* __restrict__ W,
    float* __restrict__ C, int M, int N, int K)
{
    __shared__ float As[16 * 128];
    __shared__ float Bs[16 * 64];

    const int bm = blockIdx.y * 128;
    const int bn = blockIdx.x * 64;
    const int tid = threadIdx.x;
    const int tx = tid & 15;
    const int ty = tid >> 4;

    float acc[8][4];
#pragma unroll
    for (int i = 0; i < 8; i++)
#pragma unroll
        for (int j = 0; j < 4; j++) acc[i][j] = 0.f;

    const int ar = tid >> 1, ak = (tid & 1) * 8;
    const int br = tid >> 2, bk = (tid & 3) * 4;
    const bool bval = (bn + br) < N;

    const float* Ap = A + (size_t)(bm + ar) * K + ak;
    const float* Wp = W + (size_t)(bval ? (bn + br) : 0) * K + bk;

    for (int k0 = 0; k0 < K; k0 += 16) {
        float4 a0 = *(const float4*)(Ap + k0);
        float4 a1 = *(const float4*)(Ap + k0 + 4);
        float4 bv = *(const float4*)(Wp + k0);
        if (!bval) { bv.x = bv.y = bv.z = bv.w = 0.f; }

        As[(ak + 0) * 128 + ar] = a0.x;
        As[(ak + 1) * 128 + ar] = a0.y;
        As[(ak + 2) * 128 + ar] = a0.z;
        As[(ak + 3) * 128 + ar] = a0.w;
        As[(ak + 4) * 128 + ar] = a1.x;
        As[(ak + 5) * 128 + ar] = a1.y;
        As[(ak + 6) * 128 + ar] = a1.z;
        As[(ak + 7) * 128 + ar] = a1.w;
        Bs[(bk + 0) * 64 + br] = bv.x;
        Bs[(bk + 1) * 64 + br] = bv.y;
        Bs[(bk + 2) * 64 + br] = bv.z;
        Bs[(bk + 3) * 64 + br] = bv.w;
        __syncthreads();

#pragma unroll
        for (int kk = 0; kk < 16; kk++) {
            float4 av0 = *(const float4*)&As[kk * 128 + ty * 8];
            float4 av1 = *(const float4*)&As[kk * 128 + ty * 8 + 4];
            float4 bv4 = *(const float4*)&Bs[kk * 64 + tx * 4];
            float a[8] = {av0.x, av0.y, av0.z, av0.w, av1.x, av1.y, av1.z, av1.w};
            float b[4] = {bv4.x, bv4.y, bv4.z, bv4.w};
#pragma unroll
            for (int i = 0; i < 8; i++)
#pragma unroll
                for (int j = 0; j < 4; j++)
                    acc[i][j] = fmaf(a[i], b[j], acc[i][j]);
        }
        __syncthreads();
    }

#pragma unroll
    for (int i = 0; i < 8; i++) {
        const int row = bm + ty * 8 + i;
#pragma unroll
        for (int j = 0; j < 4; j++) {
            const int col = bn + tx * 4 + j;
            if (col < N) C[(size_t)row * N + col] = acc[i][j];
        }
    }
}

// ---------------------------------------------------------------------------
// Depthwise causal conv4 + SiLU. Writes uc (M,512) and uct (CH,L).
// ---------------------------------------------------------------------------
__global__ __launch_bounds__(256) void conv_silu_kernel(
    const float* __restrict__ xz, const float* __restrict__ cw,
    const float* __restrict__ cb, float* __restrict__ uc,
    float* __restrict__ uct)
{
    __shared__ float su[35][33];
    __shared__ float so[32][33];
    const int d0 = blockIdx.x * 32;
    const int l0 = blockIdx.y * 32;
    const int b  = blockIdx.z;
    const int tx = threadIdx.x & 31;
    const int ty = threadIdx.x >> 5;

    for (int r = ty; r < 35; r += 8) {
        const int l = l0 - 3 + r;
        float v = 0.f;
        if (l >= 0) v = xz[(size_t)(b * SEQLEN + l) * 1024 + d0 + tx];
        su[r][tx] = v;
    }
    __syncthreads();

    const int d = d0 + tx;
    const float w0 = cw[d * 4 + 0], w1 = cw[d * 4 + 1];
    const float w2 = cw[d * 4 + 2], w3 = cw[d * 4 + 3];
    const float bb = cb[d];

    for (int ll = ty; ll < 32; ll += 8) {
        float acc = su[ll][tx] * w0 + su[ll + 1][tx] * w1
                  + su[ll + 2][tx] * w2 + su[ll + 3][tx] * w3 + bb;
        const float sv = acc / (1.f + __expf(-acc));
        const int m = b * SEQLEN + l0 + ll;
        uc[(size_t)m * DINNER + d] = sv;
        so[ll][tx] = sv;
    }
    __syncthreads();

    for (int dd = ty; dd < 32; dd += 8)
        uct[(size_t)(b * DINNER + d0 + dd) * SEQLEN + l0 + tx] = so[tx][dd];
}

// ---------------------------------------------------------------------------
// delta_t(CH,L) = softplus(xdbl[:, 0:16] @ dt_proj_w^T + dt_proj_b)
// ---------------------------------------------------------------------------
__global__ __launch_bounds__(256) void dtproj_kernel(
    const float* __restrict__ xdbl, const float* __restrict__ dtw,
    const float* __restrict__ dtb, float* __restrict__ deltat)
{
    __shared__ float sdt[32][17];
    __shared__ float sw[32][17];
    __shared__ float so[32][33];
    const int d0 = blockIdx.x * 32;
    const int m0 = blockIdx.y * 32;
    const int tid = threadIdx.x;

    {
        const int r = tid >> 4, c = tid & 15;
        sdt[r][c]      = xdbl[(size_t)(m0 + r) * 48 + c];
        sdt[r + 16][c] = xdbl[(size_t)(m0 + r + 16) * 48 + c];
        sw[r][c]       = dtw[(d0 + r) * 16 + c];
        sw[r + 16][c]  = dtw[(d0 + r + 16) * 16 + c];
    }
    __syncthreads();

    const int dloc = tid & 31;
    const float bias = dtb[d0 + dloc];
    for (int ll = tid >> 5; ll < 32; ll += 8) {
        float acc = bias;
#pragma unroll
        for (int k = 0; k < 16; k++) acc = fmaf(sdt[ll][k], sw[dloc][k], acc);
        so[ll][dloc] = fmaxf(acc, 0.f) + __logf(1.f + __expf(-fabsf(acc)));
    }
    __syncthreads();

    const int b  = m0 / SEQLEN;
    const int l0 = m0 % SEQLEN;
    for (int dd = tid >> 5; dd < 32; dd += 8)
        deltat[(size_t)(b * DINNER + d0 + dd) * SEQLEN + l0 + dloc] = so[dloc][dd];
}

// ---------------------------------------------------------------------------
// Selective scan. Half-warp (16 lanes) per channel, lane = state index s.
// ---------------------------------------------------------------------------
__global__ __launch_bounds__(256) void scan_kernel(
    const float* __restrict__ deltat, const float* __restrict__ uct,
    const float* __restrict__ xdbl, const float* __restrict__ Alog,
    float* __restrict__ yscant)
{
    const int warp = (blockIdx.x * blockDim.x + threadIdx.x) >> 5;
    const int lane = threadIdx.x & 31;
    const int half = lane >> 4;
    const int s    = lane & 15;
    const int ch   = warp * 2 + half;      // 0..4095
    const int b    = ch >> 9;
    const int d    = ch & 511;

    const float A = -__expf(Alog[d * DSTATE + s]);
    float state = 0.f;

    const float4* dptr4 = (const float4*)(deltat + (size_t)ch * SEQLEN);
    const float4* uptr4 = (const float4*)(uct    + (size_t)ch * SEQLEN);
    const float* xB   = xdbl + (size_t)b * SEQLEN * 48 + 16 + s;
    float* yout = yscant + (size_t)ch * SEQLEN;

    for (int l4 = 0; l4 < SEQLEN / 4; l4++) {
        const float4 dt4 = __ldg(dptr4 + l4);
        const float4 ut4 = __ldg(uptr4 + l4);
        const float dts[4] = {dt4.x, dt4.y, dt4.z, dt4.w};
        const float uts[4] = {ut4.x, ut4.y, ut4.z, ut4.w};
#pragma unroll
        for (int j = 0; j < 4; j++) {
            const float Bv = __ldg(xB);
            const float Cv = __ldg(xB + 16);
            xB += 48;
            const float dA = __expf(dts[j] * A);
            state = fmaf(state, dA, dts[j] * uts[j] * Bv);
            float p = state * Cv;
            p += __shfl_xor_sync(0xffffffffu, p, 8);
            p += __shfl_xor_sync(0xffffffffu, p, 4);
            p += __shfl_xor_sync(0xffffffffu, p, 2);
            p += __shfl_xor_sync(0xffffffffu, p, 1);
            if (s == 0) yout[l4 * 4 + j] = p;
        }
    }
}

// ---------------------------------------------------------------------------
// Gate: y = (yscan^T + D*uc) * silu(z), written as bf16 hi/lo splits.
// ---------------------------------------------------------------------------
__global__ __launch_bounds__(256) void gate_kernel(
    const float* __restrict__ yscant, const float* __restrict__ uc,
    const float* __restrict__ xz, const float* __restrict__ Dw,
    __nv_bfloat16* __restrict__ yh, __nv_bfloat16* __restrict__ yl)
{
    __shared__ float s[32][33];
    const int d0 = blockIdx.x * 32;
    const int l0 = blockIdx.y * 32;
    const int b  = blockIdx.z;
    const int tx = threadIdx.x & 31;
    const int ty = threadIdx.x >> 5;

    for (int dd = ty; dd < 32; dd += 8)
        s[dd][tx] = yscant[(size_t)(b * DINNER + d0 + dd) * SEQLEN + l0 + tx];
    __syncthreads();

    const int d = d0 + tx;
    const float Dv = Dw[d];
    for (int ll = ty; ll < 32; ll += 8) {
        const int m = b * SEQLEN + l0 + ll;
        const float ucv = uc[(size_t)m * DINNER + d];
        const float zv  = xz[(size_t)m * 1024 + DINNER + d];
        const float silu_z = zv / (1.f + __expf(-zv));
        const float v = (s[tx][ll] + Dv * ucv) * silu_z;
        const __nv_bfloat16 hv = __float2bfloat16(v);
        yh[(size_t)m * DINNER + d] = hv;
        yl[(size_t)m * DINNER + d] = __float2bfloat16(v - __bfloat162float(hv));
    }
}

// ---------------------------------------------------------------------------
// Residual + LayerNorm. Warp per row.
// ---------------------------------------------------------------------------
__global__ __launch_bounds__(256) void ln_kernel(
    const float* __restrict__ outtmp, const float* __restrict__ x,
    const float* __restrict__ g, const float* __restrict__ beta,
    float* __restrict__ out)
{
    const int warp = threadIdx.x >> 5;
    const int lane = threadIdx.x & 31;
    const int row = blockIdx.x * 8 + warp;

    float h[8];
    float sum = 0.f, sq = 0.f;
#pragma unroll
    for (int i = 0; i < 8; i++) {
        const int c = lane + i * 32;
        const float v = outtmp[(size_t)row * 256 + c] + x[(size_t)row * 256 + c];
        h[i] = v; sum += v; sq = fmaf(v, v, sq);
    }
#pragma unroll
    for (int o = 16; o; o >>= 1) {
        sum += __shfl_xor_sync(0xffffffffu, sum, o);
        sq  += __shfl_xor_sync(0xffffffffu, sq,  o);
    }
    const float mu  = sum * (1.f / 256.f);
    const float var = sq * (1.f / 256.f) - mu * mu;
    const float inv = rsqrtf(var + 1e-5f);
#pragma unroll
    for (int i = 0; i < 8; i++) {
        const int c = lane + i * 32;
        out[(size_t)row * 256 + c] = (h[i] - mu) * inv * g[c] + beta[c];
    }
}

// ---------------------------------------------------------------------------
extern "C" void kernel_launch(void* const* d_in, const int* in_sizes, int n_in,
                              void* d_out, int out_size)
{
    const float* x       = (const float*)d_in[0];
    const float* in_w    = (const float*)d_in[1];
    const float* conv_w  = (const float*)d_in[2];
    const float* conv_b  = (const float*)d_in[3];
    const float* xproj_w = (const float*)d_in[4];
    const float* dt_w    = (const float*)d_in[5];
    const float* dt_b    = (const float*)d_in[6];
    const float* A_log   = (const float*)d_in[7];
    const float* Dw      = (const float*)d_in[8];
    const float* out_w   = (const float*)d_in[9];
    const float* ln_g    = (const float*)d_in[10];
    const float* ln_b    = (const float*)d_in[11];
    float* out = (float*)d_out;

    float* base = nullptr;
    cudaGetSymbolAddress((void**)&base, g_scratch);
    float* xz     = base + OFF_XZ;
    float* uc     = base + OFF_UC;
    float* uct    = base + OFF_UCT;
    float* xdbl   = base + OFF_XDBL;
    float* deltat = base + OFF_DELTAT;
    float* yscant = base + OFF_YSCANT;
    float* outtmp = base + OFF_OUTTMP;
    __nv_bfloat16* xh  = (__nv_bfloat16*)(base + OFF_XH);
    __nv_bfloat16* xl  = (__nv_bfloat16*)(base + OFF_XL);
    __nv_bfloat16* yh  = (__nv_bfloat16*)(base + OFF_YH);
    __nv_bfloat16* yl  = (__nv_bfloat16*)(base + OFF_YL);
    __nv_bfloat16* wih = (__nv_bfloat16*)(base + OFF_WIH);
    __nv_bfloat16* wil = (__nv_bfloat16*)(base + OFF_WIL);
    __nv_bfloat16* woh = (__nv_bfloat16*)(base + OFF_WOH);
    __nv_bfloat16* wol = (__nv_bfloat16*)(base + OFF_WOL);

    // 0. pre-split fp32 -> bf16 hi/lo: x, in_w, out_w
    split_kernel<<<(MROWS * DMODEL / 4 + 255) / 256, 256>>>(
        (const float4*)x, (uint2*)xh, (uint2*)xl, MROWS * DMODEL / 4);
    split_kernel<<<(1024 * DMODEL / 4 + 255) / 256, 256>>>(
        (const float4*)in_w, (uint2*)wih, (uint2*)wil, 1024 * DMODEL / 4);
    split_kernel<<<(DMODEL * DINNER / 4 + 255) / 256, 256>>>(
        (const float4*)out_w, (uint2*)woh, (uint2*)wol, DMODEL * DINNER / 4);

    // 1. in_proj: xz = x @ in_w^T   (M=32768, N=1024, K=256) [tensor cores]
    gemm_tc4_kernel<<<dim3(1024 / 128, MROWS / 128), 256>>>(
        xh, xl, wih, wil, xz, MROWS, 1024, DMODEL);

    // 2. conv4 + SiLU (+ transpose)
    conv_silu_kernel<<<dim3(DINNER / 32, SEQLEN / 32, BATCH), 256>>>(xz, conv_w, conv_b, uc, uct);

    // 3. x_proj: xdbl = uc @ xproj_w^T   (N=48, K=512)
    sgemm_kernel<<<dim3(1, MROWS / 128), 256>>>(uc, xproj_w, xdbl, MROWS, 48, 512);

    // 4. dt_proj + softplus (transposed write)
    dtproj_kernel<<<dim3(DINNER / 32, MROWS / 32), 256>>>(xdbl, dt_w, dt_b, deltat);

    // 5. selective scan (4096 channels, 2 per warp -> 256 blocks)
    scan_kernel<<<NCH / 16, 256>>>(deltat, uct, xdbl, A_log, yscant);

    // 6. gate + skip (writes bf16 hi/lo splits of y)
    gate_kernel<<<dim3(DINNER / 32, SEQLEN / 32, BATCH), 256>>>(yscant, uc, xz, Dw, yh, yl);

    // 7. out_proj: outtmp = y @ out_w^T   (M=32768, N=256, K=512) [tensor cores]
    gemm_tc4_kernel<<<dim3(256 / 128, MROWS / 128), 256>>>(
        yh, yl, woh, wol, outtmp, MROWS, 256, DINNER);

    // 8. residual + LayerNorm
    ln_kernel<<<MROWS / 8, 256>>>(outtmp, x, ln_g, ln_b, out);
}

// round 11
// speedup vs baseline: 1.0961x; 1.0961x over previous
#include <cuda_runtime.h>
#include <cuda_bf16.h>
#include <math.h>
#include <stdint.h>

#define BATCH   8
#define SEQLEN  4096
#define DMODEL  256
#define DINNER  512
#define DSTATE  16
#define MROWS   (BATCH * SEQLEN)
#define NCH     (BATCH * DINNER)

#define OFF_XZ      0
#define SZ_XZ       (MROWS * 1024)
#define OFF_UC      (OFF_XZ + SZ_XZ)
#define SZ_UC       (MROWS * DINNER)
#define OFF_UCT     (OFF_UC + SZ_UC)
#define SZ_UCT      (NCH * SEQLEN)
#define OFF_XDBL    (OFF_UCT + SZ_UCT)
#define SZ_XDBL     (MROWS * 48)
#define OFF_DELTAT  (OFF_XDBL + SZ_XDBL)
#define SZ_DELTAT   (NCH * SEQLEN)
#define OFF_YSCANT  (OFF_DELTAT + SZ_DELTAT)
#define SZ_YSCANT   (NCH * SEQLEN)
#define OFF_OUTTMP  (OFF_YSCANT + SZ_YSCANT)
#define SZ_OUTTMP   (MROWS * DMODEL)
#define OFF_XH      (OFF_OUTTMP + SZ_OUTTMP)
#define SZ_XH       (MROWS * DMODEL / 2)
#define OFF_XL      (OFF_XH + SZ_XH)
#define OFF_YH      (OFF_XL + SZ_XH)
#define SZ_YH       (MROWS * DINNER / 2)
#define OFF_YL      (OFF_YH + SZ_YH)
#define OFF_WIH     (OFF_YL + SZ_YH)
#define SZ_WIH      (1024 * DMODEL / 2)
#define OFF_WIL     (OFF_WIH + SZ_WIH)
#define OFF_WOH     (OFF_WIL + SZ_WIH)
#define SZ_WOH      (DMODEL * DINNER / 2)
#define OFF_WOL     (OFF_WOH + SZ_WOH)
#define SCRATCH_TOTAL (OFF_WOL + SZ_WOH)

static __device__ float g_scratch[SCRATCH_TOTAL];

// ---------------- fp32 -> bf16 hi/lo split ----------------
__global__ __launch_bounds__(256) void split_kernel(
    const float4* __restrict__ src, uint2* __restrict__ h,
    uint2* __restrict__ l, int n4)
{
    const int i = blockIdx.x * blockDim.x + threadIdx.x;
    if (i >= n4) return;
    const float4 v = src[i];
    __nv_bfloat162 h0, h1, l0, l1;
    h0.x = __float2bfloat16(v.x); h0.y = __float2bfloat16(v.y);
    h1.x = __float2bfloat16(v.z); h1.y = __float2bfloat16(v.w);
    l0.x = __float2bfloat16(v.x - __bfloat162float(h0.x));
    l0.y = __float2bfloat16(v.y - __bfloat162float(h0.y));
    l1.x = __float2bfloat16(v.z - __bfloat162float(h1.x));
    l1.y = __float2bfloat16(v.w - __bfloat162float(h1.y));
    h[i] = make_uint2(*(uint32_t*)&h0, *(uint32_t*)&h1);
    l[i] = make_uint2(*(uint32_t*)&l0, *(uint32_t*)&l1);
}

// ---------------- TC GEMM: k32 tile, cp.async 2-stage, 80KB dynamic ----------
__device__ __forceinline__ void mma_bf16(float* c, const uint32_t* a,
                                         uint32_t b0, uint32_t b1)
{
    asm volatile(
        "mma.sync.aligned.m16n8k16.row.col.f32.bf16.bf16.f32 "
        "{%0,%1,%2,%3}, {%4,%5,%6,%7}, {%8,%9}, {%0,%1,%2,%3};"
        : "+f"(c[0]), "+f"(c[1]), "+f"(c[2]), "+f"(c[3])
        : "r"(a[0]), "r"(a[1]), "r"(a[2]), "r"(a[3]), "r"(b0), "r"(b1));
}

__device__ __forceinline__ void cp16(uint32_t smem_addr, const void* gptr)
{
    asm volatile("cp.async.ca.shared.global [%0], [%1], 16;"
                 :: "r"(smem_addr), "l"(gptr));
}

#define SPAD 20
#define GTC_SMEM_BYTES (2 * 4 * 128 * SPAD * 4)   // 81920

__global__ __launch_bounds__(256, 2) void gemm_tc3_kernel(
    const __nv_bfloat16* __restrict__ Ah_, const __nv_bfloat16* __restrict__ Al_,
    const __nv_bfloat16* __restrict__ Wh_, const __nv_bfloat16* __restrict__ Wl_,
    float* __restrict__ C, int M, int N, int K)
{
    extern __shared__ uint32_t smem[];   // [stage][arr][row][SPAD]
    const uint32_t smem_base = (uint32_t)__cvta_generic_to_shared(smem);

    const int bm = blockIdx.y * 128;
    const int bn = blockIdx.x * 128;
    const int tid = threadIdx.x;
    const int lane = tid & 31;
    const int g   = lane >> 2;
    const int tig = lane & 3;
    const int w   = tid >> 5;
    const int wm  = (w >> 1) * 32;
    const int wn  = (w & 1) * 64;

    const int frow = tid >> 1;
    const int fcol = (tid & 1) * 16;
    const int pbase = (tid & 1) * 8;

    const __nv_bfloat16* gp[4];
    gp[0] = Ah_ + (size_t)(bm + frow) * K + fcol;
    gp[1] = Al_ + (size_t)(bm + frow) * K + fcol;
    gp[2] = Wh_ + (size_t)(bn + frow) * K + fcol;
    gp[3] = Wl_ + (size_t)(bn + frow) * K + fcol;

    const uint32_t arrStride = 128 * SPAD * 4;
    const uint32_t stStride  = 4 * arrStride;
    const uint32_t rowOff    = (uint32_t)frow * (SPAD * 4) + pbase * 4;

    float acc[2][8][4];
#pragma unroll
    for (int i = 0; i < 2; i++)
#pragma unroll
        for (int j = 0; j < 8; j++)
#pragma unroll
            for (int q = 0; q < 4; q++) acc[i][j][q] = 0.f;

    const int KT = K >> 5;

    auto issue = [&](int kt, int st) {
        const int o = kt * 32;
        const uint32_t sb = smem_base + (uint32_t)st * stStride + rowOff;
#pragma unroll
        for (int a = 0; a < 4; a++) {
            cp16(sb + a * arrStride,      gp[a] + o);
            cp16(sb + a * arrStride + 16, gp[a] + o + 8);
        }
    };

    issue(0, 0);
    asm volatile("cp.async.commit_group;");

    for (int kt = 0; kt < KT; kt++) {
        const int st = kt & 1;
        if (kt + 1 < KT) {
            issue(kt + 1, st ^ 1);
            asm volatile("cp.async.commit_group;");
            asm volatile("cp.async.wait_group 1;");
        } else {
            asm volatile("cp.async.wait_group 0;");
        }
        __syncthreads();

        const uint32_t* sAh = smem + (size_t)st * (4 * 128 * SPAD);
        const uint32_t* sAl = sAh + 128 * SPAD;
        const uint32_t* sWh = sAl + 128 * SPAD;
        const uint32_t* sWl = sWh + 128 * SPAD;

#pragma unroll
        for (int ks = 0; ks < 2; ks++) {
            const int kp = ks * 8 + tig;
            uint32_t ah[2][4], al[2][4];
#pragma unroll
            for (int im = 0; im < 2; im++) {
                const int r = wm + im * 16 + g;
                ah[im][0] = sAh[r * SPAD + kp];           al[im][0] = sAl[r * SPAD + kp];
                ah[im][1] = sAh[(r + 8) * SPAD + kp];     al[im][1] = sAl[(r + 8) * SPAD + kp];
                ah[im][2] = sAh[r * SPAD + kp + 4];       al[im][2] = sAl[r * SPAD + kp + 4];
                ah[im][3] = sAh[(r + 8) * SPAD + kp + 4]; al[im][3] = sAl[(r + 8) * SPAD + kp + 4];
            }
#pragma unroll
            for (int jn = 0; jn < 8; jn++) {
                const int nr = wn + jn * 8 + g;
                const uint32_t bh0 = sWh[nr * SPAD + kp], bh1 = sWh[nr * SPAD + kp + 4];
                const uint32_t bl0 = sWl[nr * SPAD + kp], bl1 = sWl[nr * SPAD + kp + 4];
#pragma unroll
                for (int im = 0; im < 2; im++) {
                    mma_bf16(acc[im][jn], ah[im], bh0, bh1);
                    mma_bf16(acc[im][jn], ah[im], bl0, bl1);
                    mma_bf16(acc[im][jn], al[im], bh0, bh1);
                }
            }
        }
        __syncthreads();
    }

#pragma unroll
    for (int im = 0; im < 2; im++) {
        const int row = bm + wm + im * 16 + g;
#pragma unroll
        for (int jn = 0; jn < 8; jn++) {
            const int col = bn + wn + jn * 8 + 2 * tig;
            *(float2*)(C + (size_t)row * N + col) =
                make_float2(acc[im][jn][0], acc[im][jn][1]);
            *(float2*)(C + (size_t)(row + 8) * N + col) =
                make_float2(acc[im][jn][2], acc[im][jn][3]);
        }
    }
}

// ---------------- SGEMM for x_proj (N=48) ----------------
__global__ __launch_bounds__(256) void sgemm_kernel(
    const float* __restrict__ A, const float* __restrict__ W,
    float* __restrict__ C, int M, int N, int K)
{
    __shared__ float As[16 * 128];
    __shared__ float Bs[16 * 64];

    const int bm = blockIdx.y * 128;
    const int bn = blockIdx.x * 64;
    const int tid = threadIdx.x;
    const int tx = tid & 15;
    const int ty = tid >> 4;

    float acc[8][4];
#pragma unroll
    for (int i = 0; i < 8; i++)
#pragma unroll
        for (int j = 0; j < 4; j++) acc[i][j] = 0.f;

    const int ar = tid >> 1, ak = (tid & 1) * 8;
    const int br = tid >> 2, bk = (tid & 3) * 4;
    const bool bval = (bn + br) < N;

    const float* Ap = A + (size_t)(bm + ar) * K + ak;
    const float* Wp = W + (size_t)(bval ? (bn + br) : 0) * K + bk;

    for (int k0 = 0; k0 < K; k0 += 16) {
        float4 a0 = *(const float4*)(Ap + k0);
        float4 a1 = *(const float4*)(Ap + k0 + 4);
        float4 bv = *(const float4*)(Wp + k0);
        if (!bval) { bv.x = bv.y = bv.z = bv.w = 0.f; }

        As[(ak + 0) * 128 + ar] = a0.x;
        As[(ak + 1) * 128 + ar] = a0.y;
        As[(ak + 2) * 128 + ar] = a0.z;
        As[(ak + 3) * 128 + ar] = a0.w;
        As[(ak + 4) * 128 + ar] = a1.x;
        As[(ak + 5) * 128 + ar] = a1.y;
        As[(ak + 6) * 128 + ar] = a1.z;
        As[(ak + 7) * 128 + ar] = a1.w;
        Bs[(bk + 0) * 64 + br] = bv.x;
        Bs[(bk + 1) * 64 + br] = bv.y;
        Bs[(bk + 2) * 64 + br] = bv.z;
        Bs[(bk + 3) * 64 + br] = bv.w;
        __syncthreads();

#pragma unroll
        for (int kk = 0; kk < 16; kk++) {
            float4 av0 = *(const float4*)&As[kk * 128 + ty * 8];
            float4 av1 = *(const float4*)&As[kk * 128 + ty * 8 + 4];
            float4 bv4 = *(const float4*)&Bs[kk * 64 + tx * 4];
            float a[8] = {av0.x, av0.y, av0.z, av0.w, av1.x, av1.y, av1.z, av1.w};
            float b[4] = {bv4.x, bv4.y, bv4.z, bv4.w};
#pragma unroll
            for (int i = 0; i < 8; i++)
#pragma unroll
                for (int j = 0; j < 4; j++)
                    acc[i][j] = fmaf(a[i], b[j], acc[i][j]);
        }
        __syncthreads();
    }

#pragma unroll
    for (int i = 0; i < 8; i++) {
        const int row = bm + ty * 8 + i;
#pragma unroll
        for (int j = 0; j < 4; j++) {
            const int col = bn + tx * 4 + j;
            if (col < N) C[(size_t)row * N + col] = acc[i][j];
        }
    }
}

// ---------------- conv4 + SiLU (+ transpose) ----------------
__global__ __launch_bounds__(256) void conv_silu_kernel(
    const float* __restrict__ xz, const float* __restrict__ cw,
    const float* __restrict__ cb, float* __restrict__ uc,
    float* __restrict__ uct)
{
    __shared__ float su[35][33];
    __shared__ float so[32][33];
    const int d0 = blockIdx.x * 32;
    const int l0 = blockIdx.y * 32;
    const int b  = blockIdx.z;
    const int tx = threadIdx.x & 31;
    const int ty = threadIdx.x >> 5;

    for (int r = ty; r < 35; r += 8) {
        const int l = l0 - 3 + r;
        float v = 0.f;
        if (l >= 0) v = xz[(size_t)(b * SEQLEN + l) * 1024 + d0 + tx];
        su[r][tx] = v;
    }
    __syncthreads();

    const int d = d0 + tx;
    const float w0 = cw[d * 4 + 0], w1 = cw[d * 4 + 1];
    const float w2 = cw[d * 4 + 2], w3 = cw[d * 4 + 3];
    const float bb = cb[d];

    for (int ll = ty; ll < 32; ll += 8) {
        float acc = su[ll][tx] * w0 + su[ll + 1][tx] * w1
                  + su[ll + 2][tx] * w2 + su[ll + 3][tx] * w3 + bb;
        const float sv = acc / (1.f + __expf(-acc));
        const int m = b * SEQLEN + l0 + ll;
        uc[(size_t)m * DINNER + d] = sv;
        so[ll][tx] = sv;
    }
    __syncthreads();

    for (int dd = ty; dd < 32; dd += 8)
        uct[(size_t)(b * DINNER + d0 + dd) * SEQLEN + l0 + tx] = so[tx][dd];
}

// ---------------- dt_proj + softplus (transposed) ----------------
__global__ __launch_bounds__(256) void dtproj_kernel(
    const float* __restrict__ xdbl, const float* __restrict__ dtw,
    const float* __restrict__ dtb, float* __restrict__ deltat)
{
    __shared__ float sdt[32][17];
    __shared__ float sw[32][17];
    __shared__ float so[32][33];
    const int d0 = blockIdx.x * 32;
    const int m0 = blockIdx.y * 32;
    const int tid = threadIdx.x;

    {
        const int r = tid >> 4, c = tid & 15;
        sdt[r][c]      = xdbl[(size_t)(m0 + r) * 48 + c];
        sdt[r + 16][c] = xdbl[(size_t)(m0 + r + 16) * 48 + c];
        sw[r][c]       = dtw[(d0 + r) * 16 + c];
        sw[r + 16][c]  = dtw[(d0 + r + 16) * 16 + c];
    }
    __syncthreads();

    const int dloc = tid & 31;
    const float bias = dtb[d0 + dloc];
    for (int ll = tid >> 5; ll < 32; ll += 8) {
        float acc = bias;
#pragma unroll
        for (int k = 0; k < 16; k++) acc = fmaf(sdt[ll][k], sw[dloc][k], acc);
        so[ll][dloc] = fmaxf(acc, 0.f) + __logf(1.f + __expf(-fabsf(acc)));
    }
    __syncthreads();

    const int b  = m0 / SEQLEN;
    const int l0 = m0 % SEQLEN;
    for (int dd = tid >> 5; dd < 32; dd += 8)
        deltat[(size_t)(b * DINNER + d0 + dd) * SEQLEN + l0 + dloc] = so[dloc][dd];
}

// ---------------- selective scan: blocked-16 + register transpose-reduce ----
// Half-warp per channel, lane = state s. Per 16-step block: accumulate
// p[16] partials, then 15-shfl tree so lane s holds y[l0+s] (coalesced STG).
__global__ __launch_bounds__(256) void scan_kernel(
    const float* __restrict__ deltat, const float* __restrict__ uct,
    const float* __restrict__ xdbl, const float* __restrict__ Alog,
    float* __restrict__ yscant)
{
    const int warp = (blockIdx.x * blockDim.x + threadIdx.x) >> 5;
    const int lane = threadIdx.x & 31;
    const int half = lane >> 4;
    const int s    = lane & 15;
    const int ch   = warp * 2 + half;
    const int b    = ch >> 9;
    const int d    = ch & 511;

    const float A = -__expf(Alog[d * DSTATE + s]);
    float state = 0.f;

    const float4* dp4 = (const float4*)(deltat + (size_t)ch * SEQLEN);
    const float4* up4 = (const float4*)(uct    + (size_t)ch * SEQLEN);
    const float* xB   = xdbl + (size_t)b * SEQLEN * 48 + 16 + s;
    float* yout = yscant + (size_t)ch * SEQLEN;

    for (int l0 = 0; l0 < SEQLEN; l0 += 16) {
        float p[16];
        const int q0 = l0 >> 2;
#pragma unroll
        for (int blk = 0; blk < 4; blk++) {
            const float4 dt4 = __ldg(dp4 + q0 + blk);
            const float4 ut4 = __ldg(up4 + q0 + blk);
            const float dts[4] = {dt4.x, dt4.y, dt4.z, dt4.w};
            const float uts[4] = {ut4.x, ut4.y, ut4.z, ut4.w};
#pragma unroll
            for (int j = 0; j < 4; j++) {
                const float Bv = __ldg(xB);
                const float Cv = __ldg(xB + 16);
                xB += 48;
                const float dA = __expf(dts[j] * A);
                state = fmaf(state, dA, dts[j] * uts[j] * Bv);
                p[blk * 4 + j] = state * Cv;
            }
        }
        // lane-transpose reduce: after 4 rounds lane s holds sum over all
        // 16 lanes for step index s.
        float q8[8];
#pragma unroll
        for (int j = 0; j < 8; j++) {
            const float send = (s & 8) ? p[j] : p[j + 8];
            const float r = __shfl_xor_sync(0xffffffffu, send, 8);
            q8[j] = ((s & 8) ? p[j + 8] : p[j]) + r;
        }
        float q4[4];
#pragma unroll
        for (int j = 0; j < 4; j++) {
            const float send = (s & 4) ? q8[j] : q8[j + 4];
            const float r = __shfl_xor_sync(0xffffffffu, send, 4);
            q4[j] = ((s & 4) ? q8[j + 4] : q8[j]) + r;
        }
        float q2[2];
#pragma unroll
        for (int j = 0; j < 2; j++) {
            const float send = (s & 2) ? q4[j] : q4[j + 2];
            const float r = __shfl_xor_sync(0xffffffffu, send, 2);
            q2[j] = ((s & 2) ? q4[j + 2] : q4[j]) + r;
        }
        {
            const float send = (s & 1) ? q2[0] : q2[1];
            const float r = __shfl_xor_sync(0xffffffffu, send, 1);
            yout[l0 + s] = ((s & 1) ? q2[1] : q2[0]) + r;
        }
    }
}

// ---------------- gate (+ bf16 hi/lo split of y) ----------------
__global__ __launch_bounds__(256) void gate_kernel(
    const float* __restrict__ yscant, const float* __restrict__ uc,
    const float* __restrict__ xz, const float* __restrict__ Dw,
    __nv_bfloat16* __restrict__ yh, __nv_bfloat16* __restrict__ yl)
{
    __shared__ float s[32][33];
    const int d0 = blockIdx.x * 32;
    const int l0 = blockIdx.y * 32;
    const int b  = blockIdx.z;
    const int tx = threadIdx.x & 31;
    const int ty = threadIdx.x >> 5;

    for (int dd = ty; dd < 32; dd += 8)
        s[dd][tx] = yscant[(size_t)(b * DINNER + d0 + dd) * SEQLEN + l0 + tx];
    __syncthreads();

    const int d = d0 + tx;
    const float Dv = Dw[d];
    for (int ll = ty; ll < 32; ll += 8) {
        const int m = b * SEQLEN + l0 + ll;
        const float ucv = uc[(size_t)m * DINNER + d];
        const float zv  = xz[(size_t)m * 1024 + DINNER + d];
        const float silu_z = zv / (1.f + __expf(-zv));
        const float v = (s[tx][ll] + Dv * ucv) * silu_z;
        const __nv_bfloat16 hv = __float2bfloat16(v);
        yh[(size_t)m * DINNER + d] = hv;
        yl[(size_t)m * DINNER + d] = __float2bfloat16(v - __bfloat162float(hv));
    }
}

// ---------------- residual + LayerNorm ----------------
__global__ __launch_bounds__(256) void ln_kernel(
    const float* __restrict__ outtmp, const float* __restrict__ x,
    const float* __restrict__ g, const float* __restrict__ beta,
    float* __restrict__ out)
{
    const int warp = threadIdx.x >> 5;
    const int lane = threadIdx.x & 31;
    const int row = blockIdx.x * 8 + warp;

    float h[8];
    float sum = 0.f, sq = 0.f;
#pragma unroll
    for (int i = 0; i < 8; i++) {
        const int c = lane + i * 32;
        const float v = outtmp[(size_t)row * 256 + c] + x[(size_t)row * 256 + c];
        h[i] = v; sum += v; sq = fmaf(v, v, sq);
    }
#pragma unroll
    for (int o = 16; o; o >>= 1) {
        sum += __shfl_xor_sync(0xffffffffu, sum, o);
        sq  += __shfl_xor_sync(0xffffffffu, sq,  o);
    }
    const float mu  = sum * (1.f / 256.f);
    const float var = sq * (1.f / 256.f) - mu * mu;
    const float inv = rsqrtf(var + 1e-5f);
#pragma unroll
    for (int i = 0; i < 8; i++) {
        const int c = lane + i * 32;
        out[(size_t)row * 256 + c] = (h[i] - mu) * inv * g[c] + beta[c];
    }
}

// ---------------------------------------------------------------------------
extern "C" void kernel_launch(void* const* d_in, const int* in_sizes, int n_in,
                              void* d_out, int out_size)
{
    const float* x       = (const float*)d_in[0];
    const float* in_w    = (const float*)d_in[1];
    const float* conv_w  = (const float*)d_in[2];
    const float* conv_b  = (const float*)d_in[3];
    const float* xproj_w = (const float*)d_in[4];
    const float* dt_w    = (const float*)d_in[5];
    const float* dt_b    = (const float*)d_in[6];
    const float* A_log   = (const float*)d_in[7];
    const float* Dw      = (const float*)d_in[8];
    const float* out_w   = (const float*)d_in[9];
    const float* ln_g    = (const float*)d_in[10];
    const float* ln_b    = (const float*)d_in[11];
    float* out = (float*)d_out;

    float* base = nullptr;
    cudaGetSymbolAddress((void**)&base, g_scratch);
    float* xz     = base + OFF_XZ;
    float* uc     = base + OFF_UC;
    float* uct    = base + OFF_UCT;
    float* xdbl   = base + OFF_XDBL;
    float* deltat = base + OFF_DELTAT;
    float* yscant = base + OFF_YSCANT;
    float* outtmp = base + OFF_OUTTMP;
    __nv_bfloat16* xh  = (__nv_bfloat16*)(base + OFF_XH);
    __nv_bfloat16* xl  = (__nv_bfloat16*)(base + OFF_XL);
    __nv_bfloat16* yh  = (__nv_bfloat16*)(base + OFF_YH);
    __nv_bfloat16* yl  = (__nv_bfloat16*)(base + OFF_YL);
    __nv_bfloat16* wih = (__nv_bfloat16*)(base + OFF_WIH);
    __nv_bfloat16* wil = (__nv_bfloat16*)(base + OFF_WIL);
    __nv_bfloat16* woh = (__nv_bfloat16*)(base + OFF_WOH);
    __nv_bfloat16* wol = (__nv_bfloat16*)(base + OFF_WOL);

    cudaFuncSetAttribute(gemm_tc3_kernel,
                         cudaFuncAttributeMaxDynamicSharedMemorySize,
                         GTC_SMEM_BYTES);

    split_kernel<<<(MROWS * DMODEL / 4 + 255) / 256, 256>>>(
        (const float4*)x, (uint2*)xh, (uint2*)xl, MROWS * DMODEL / 4);
    split_kernel<<<(1024 * DMODEL / 4 + 255) / 256, 256>>>(
        (const float4*)in_w, (uint2*)wih, (uint2*)wil, 1024 * DMODEL / 4);
    split_kernel<<<(DMODEL * DINNER / 4 + 255) / 256, 256>>>(
        (const float4*)out_w, (uint2*)woh, (uint2*)wol, DMODEL * DINNER / 4);

    gemm_tc3_kernel<<<dim3(1024 / 128, MROWS / 128), 256, GTC_SMEM_BYTES>>>(
        xh, xl, wih, wil, xz, MROWS, 1024, DMODEL);

    conv_silu_kernel<<<dim3(DINNER / 32, SEQLEN / 32, BATCH), 256>>>(
        xz, conv_w, conv_b, uc, uct);

    sgemm_kernel<<<dim3(1, MROWS / 128), 256>>>(uc, xproj_w, xdbl, MROWS, 48, 512);

    dtproj_kernel<<<dim3(DINNER / 32, MROWS / 32), 256>>>(xdbl, dt_w, dt_b, deltat);

    scan_kernel<<<NCH / 16, 256>>>(deltat, uct, xdbl, A_log, yscant);

    gate_kernel<<<dim3(DINNER / 32, SEQLEN / 32, BATCH), 256>>>(
        yscant, uc, xz, Dw, yh, yl);

    gemm_tc3_kernel<<<dim3(256 / 128, MROWS / 128), 256, GTC_SMEM_BYTES>>>(
        yh, yl, woh, wol, outtmp, MROWS, 256, DINNER);

    ln_kernel<<<MROWS / 8, 256>>>(outtmp, x, ln_g, ln_b, out);
}

// round 13
// speedup vs baseline: 1.1306x; 1.0315x over previous
#include <cuda_runtime.h>
#include <cuda_bf16.h>
#include <math.h>
#include <stdint.h>

#define BATCH   8
#define SEQLEN  4096
#define DMODEL  256
#define DINNER  512
#define DSTATE  16
#define MROWS   (BATCH * SEQLEN)
#define NCH     (BATCH * DINNER)

#define OFF_XZ      0
#define SZ_XZ       (MROWS * 1024)
#define OFF_UC      (OFF_XZ + SZ_XZ)
#define SZ_UC       (MROWS * DINNER)
#define OFF_UCT     (OFF_UC + SZ_UC)
#define SZ_UCT      (NCH * SEQLEN)
#define OFF_XDBL    (OFF_UCT + SZ_UCT)
#define SZ_XDBL     (MROWS * 48)
#define OFF_DELTAT  (OFF_XDBL + SZ_XDBL)
#define SZ_DELTAT   (NCH * SEQLEN)
#define OFF_YSCANT  (OFF_DELTAT + SZ_DELTAT)
#define SZ_YSCANT   (NCH * SEQLEN)
#define OFF_OUTTMP  (OFF_YSCANT + SZ_YSCANT)
#define SZ_OUTTMP   (MROWS * DMODEL)
#define OFF_XH      (OFF_OUTTMP + SZ_OUTTMP)
#define SZ_XH       (MROWS * DMODEL / 2)
#define OFF_XL      (OFF_XH + SZ_XH)
#define OFF_YH      (OFF_XL + SZ_XH)
#define SZ_YH       (MROWS * DINNER / 2)
#define OFF_YL      (OFF_YH + SZ_YH)
#define OFF_WIH     (OFF_YL + SZ_YH)
#define SZ_WIH      (1024 * DMODEL / 2)
#define OFF_WIL     (OFF_WIH + SZ_WIH)
#define OFF_WOH     (OFF_WIL + SZ_WIH)
#define SZ_WOH      (DMODEL * DINNER / 2)
#define OFF_WOL     (OFF_WOH + SZ_WOH)
#define SCRATCH_TOTAL (OFF_WOL + SZ_WOH)

static __device__ float g_scratch[SCRATCH_TOTAL];

// ---------------- fp32 -> bf16 hi/lo split ----------------
__global__ __launch_bounds__(256) void split_kernel(
    const float4* __restrict__ src, uint2* __restrict__ h,
    uint2* __restrict__ l, int n4)
{
    const int i = blockIdx.x * blockDim.x + threadIdx.x;
    if (i >= n4) return;
    const float4 v = src[i];
    __nv_bfloat162 h0, h1, l0, l1;
    h0.x = __float2bfloat16(v.x); h0.y = __float2bfloat16(v.y);
    h1.x = __float2bfloat16(v.z); h1.y = __float2bfloat16(v.w);
    l0.x = __float2bfloat16(v.x - __bfloat162float(h0.x));
    l0.y = __float2bfloat16(v.y - __bfloat162float(h0.y));
    l1.x = __float2bfloat16(v.z - __bfloat162float(h1.x));
    l1.y = __float2bfloat16(v.w - __bfloat162float(h1.y));
    h[i] = make_uint2(*(uint32_t*)&h0, *(uint32_t*)&h1);
    l[i] = make_uint2(*(uint32_t*)&l0, *(uint32_t*)&l1);
}

// ---------------- TC GEMM: k32, cp.async 2-stage, ldmatrix fragments -------
__device__ __forceinline__ void mma_bf16(float* c, const uint32_t* a,
                                         uint32_t b0, uint32_t b1)
{
    asm volatile(
        "mma.sync.aligned.m16n8k16.row.col.f32.bf16.bf16.f32 "
        "{%0,%1,%2,%3}, {%4,%5,%6,%7}, {%8,%9}, {%0,%1,%2,%3};"
        : "+f"(c[0]), "+f"(c[1]), "+f"(c[2]), "+f"(c[3])
        : "r"(a[0]), "r"(a[1]), "r"(a[2]), "r"(a[3]), "r"(b0), "r"(b1));
}

__device__ __forceinline__ void cp16(uint32_t s, const void* g)
{
    asm volatile("cp.async.ca.shared.global [%0], [%1], 16;" :: "r"(s), "l"(g));
}

__device__ __forceinline__ void ldsm4(uint32_t* r, uint32_t addr)
{
    asm volatile("ldmatrix.sync.aligned.m8n8.x4.shared.b16 {%0,%1,%2,%3}, [%4];"
                 : "=r"(r[0]), "=r"(r[1]), "=r"(r[2]), "=r"(r[3]) : "r"(addr));
}

#define SPAD 20
#define GTC_SMEM_BYTES (2 * 4 * 128 * SPAD * 4)   // 81920

__global__ __launch_bounds__(256, 2) void gemm_tc3_kernel(
    const __nv_bfloat16* __restrict__ Ah_, const __nv_bfloat16* __restrict__ Al_,
    const __nv_bfloat16* __restrict__ Wh_, const __nv_bfloat16* __restrict__ Wl_,
    float* __restrict__ C, int M, int N, int K)
{
    extern __shared__ uint32_t smem[];   // [stage][arr][row][SPAD]
    const uint32_t smem_base = (uint32_t)__cvta_generic_to_shared(smem);

    const int bm = blockIdx.y * 128;
    const int bn = blockIdx.x * 128;
    const int tid = threadIdx.x;
    const int lane = tid & 31;
    const int tig = lane & 3;
    const int w   = tid >> 5;
    const int wm  = (w >> 1) * 32;
    const int wn  = (w & 1) * 64;

    const int frow = tid >> 1;
    const int fcol = (tid & 1) * 16;
    const int pbase = (tid & 1) * 8;

    const __nv_bfloat16* gp[4];
    gp[0] = Ah_ + (size_t)(bm + frow) * K + fcol;
    gp[1] = Al_ + (size_t)(bm + frow) * K + fcol;
    gp[2] = Wh_ + (size_t)(bn + frow) * K + fcol;
    gp[3] = Wl_ + (size_t)(bn + frow) * K + fcol;

    const uint32_t arrStride = 128 * SPAD * 4;
    const uint32_t stStride  = 4 * arrStride;
    const uint32_t rowOff    = (uint32_t)frow * (SPAD * 4) + pbase * 4;

    // ldmatrix per-lane addressing: lanes 0-15 -> rows, lanes 16-31 -> k-half 1
    const uint32_t laneRow = lane & 15;
    const uint32_t kSel    = (lane >> 4) * 16;   // bytes (4 words)
    const uint32_t aRow0   = (wm + laneRow) * (SPAD * 4);
    const uint32_t aRow1   = (wm + 16 + laneRow) * (SPAD * 4);
    const uint32_t bRowB   = (wn + laneRow) * (SPAD * 4);

    float acc[2][8][4];
#pragma unroll
    for (int i = 0; i < 2; i++)
#pragma unroll
        for (int j = 0; j < 8; j++)
#pragma unroll
            for (int q = 0; q < 4; q++) acc[i][j][q] = 0.f;

    const int KT = K >> 5;

    auto issue = [&](int kt, int st) {
        const int o = kt * 32;
        const uint32_t sb = smem_base + (uint32_t)st * stStride + rowOff;
#pragma unroll
        for (int a = 0; a < 4; a++) {
            cp16(sb + a * arrStride,      gp[a] + o);
            cp16(sb + a * arrStride + 16, gp[a] + o + 8);
        }
    };

    issue(0, 0);
    asm volatile("cp.async.commit_group;");

    for (int kt = 0; kt < KT; kt++) {
        const int st = kt & 1;
        if (kt + 1 < KT) {
            issue(kt + 1, st ^ 1);
            asm volatile("cp.async.commit_group;");
            asm volatile("cp.async.wait_group 1;");
        } else {
            asm volatile("cp.async.wait_group 0;");
        }
        __syncthreads();

        const uint32_t sb = smem_base + (uint32_t)st * stStride;

#pragma unroll
        for (int ks = 0; ks < 2; ks++) {
            const uint32_t kOff = ks * 32 + kSel;   // bytes within row
            uint32_t ah[2][4], al[2][4];
            {
                const uint32_t ra0 = sb + aRow0 + kOff;
                const uint32_t ra1 = sb + aRow1 + kOff;
                ldsm4(ah[0], ra0);
                ldsm4(al[0], ra0 + arrStride);
                ldsm4(ah[1], ra1);
                ldsm4(al[1], ra1 + arrStride);
            }
#pragma unroll
            for (int jn2 = 0; jn2 < 4; jn2++) {
                const uint32_t rb = sb + 2 * arrStride + bRowB
                                  + jn2 * (16 * SPAD * 4) + kOff;
                uint32_t bh[4], bl[4];
                ldsm4(bh, rb);
                ldsm4(bl, rb + arrStride);
#pragma unroll
                for (int sel = 0; sel < 2; sel++) {
                    const int jn = jn2 * 2 + sel;
                    const uint32_t bh0 = bh[sel], bh1 = bh[2 + sel];
                    const uint32_t bl0 = bl[sel], bl1 = bl[2 + sel];
#pragma unroll
                    for (int im = 0; im < 2; im++) {
                        mma_bf16(acc[im][jn], ah[im], bh0, bh1);
                        mma_bf16(acc[im][jn], ah[im], bl0, bl1);
                        mma_bf16(acc[im][jn], al[im], bh0, bh1);
                    }
                }
            }
        }
        __syncthreads();
    }

    const int g = lane >> 2;
#pragma unroll
    for (int im = 0; im < 2; im++) {
        const int row = bm + wm + im * 16 + g;
#pragma unroll
        for (int jn = 0; jn < 8; jn++) {
            const int col = bn + wn + jn * 8 + 2 * tig;
            *(float2*)(C + (size_t)row * N + col) =
                make_float2(acc[im][jn][0], acc[im][jn][1]);
            *(float2*)(C + (size_t)(row + 8) * N + col) =
                make_float2(acc[im][jn][2], acc[im][jn][3]);
        }
    }
}

// ---------------- SGEMM for x_proj (N=48) ----------------
__global__ __launch_bounds__(256) void sgemm_kernel(
    const float* __restrict__ A, const float* __restrict__ W,
    float* __restrict__ C, int M, int N, int K)
{
    __shared__ float As[16 * 128];
    __shared__ float Bs[16 * 64];

    const int bm = blockIdx.y * 128;
    const int bn = blockIdx.x * 64;
    const int tid = threadIdx.x;
    const int tx = tid & 15;
    const int ty = tid >> 4;

    float acc[8][4];
#pragma unroll
    for (int i = 0; i < 8; i++)
#pragma unroll
        for (int j = 0; j < 4; j++) acc[i][j] = 0.f;

    const int ar = tid >> 1, ak = (tid & 1) * 8;
    const int br = tid >> 2, bk = (tid & 3) * 4;
    const bool bval = (bn + br) < N;

    const float* Ap = A + (size_t)(bm + ar) * K + ak;
    const float* Wp = W + (size_t)(bval ? (bn + br) : 0) * K + bk;

    for (int k0 = 0; k0 < K; k0 += 16) {
        float4 a0 = *(const float4*)(Ap + k0);
        float4 a1 = *(const float4*)(Ap + k0 + 4);
        float4 bv = *(const float4*)(Wp + k0);
        if (!bval) { bv.x = bv.y = bv.z = bv.w = 0.f; }

        As[(ak + 0) * 128 + ar] = a0.x;
        As[(ak + 1) * 128 + ar] = a0.y;
        As[(ak + 2) * 128 + ar] = a0.z;
        As[(ak + 3) * 128 + ar] = a0.w;
        As[(ak + 4) * 128 + ar] = a1.x;
        As[(ak + 5) * 128 + ar] = a1.y;
        As[(ak + 6) * 128 + ar] = a1.z;
        As[(ak + 7) * 128 + ar] = a1.w;
        Bs[(bk + 0) * 64 + br] = bv.x;
        Bs[(bk + 1) * 64 + br] = bv.y;
        Bs[(bk + 2) * 64 + br] = bv.z;
        Bs[(bk + 3) * 64 + br] = bv.w;
        __syncthreads();

#pragma unroll
        for (int kk = 0; kk < 16; kk++) {
            float4 av0 = *(const float4*)&As[kk * 128 + ty * 8];
            float4 av1 = *(const float4*)&As[kk * 128 + ty * 8 + 4];
            float4 bv4 = *(const float4*)&Bs[kk * 64 + tx * 4];
            float a[8] = {av0.x, av0.y, av0.z, av0.w, av1.x, av1.y, av1.z, av1.w};
            float b[4] = {bv4.x, bv4.y, bv4.z, bv4.w};
#pragma unroll
            for (int i = 0; i < 8; i++)
#pragma unroll
                for (int j = 0; j < 4; j++)
                    acc[i][j] = fmaf(a[i], b[j], acc[i][j]);
        }
        __syncthreads();
    }

#pragma unroll
    for (int i = 0; i < 8; i++) {
        const int row = bm + ty * 8 + i;
#pragma unroll
        for (int j = 0; j < 4; j++) {
            const int col = bn + tx * 4 + j;
            if (col < N) C[(size_t)row * N + col] = acc[i][j];
        }
    }
}

// ---------------- conv4 + SiLU (+ transpose) ----------------
__global__ __launch_bounds__(256) void conv_silu_kernel(
    const float* __restrict__ xz, const float* __restrict__ cw,
    const float* __restrict__ cb, float* __restrict__ uc,
    float* __restrict__ uct)
{
    __shared__ float su[35][33];
    __shared__ float so[32][33];
    const int d0 = blockIdx.x * 32;
    const int l0 = blockIdx.y * 32;
    const int b  = blockIdx.z;
    const int tx = threadIdx.x & 31;
    const int ty = threadIdx.x >> 5;

    for (int r = ty; r < 35; r += 8) {
        const int l = l0 - 3 + r;
        float v = 0.f;
        if (l >= 0) v = xz[(size_t)(b * SEQLEN + l) * 1024 + d0 + tx];
        su[r][tx] = v;
    }
    __syncthreads();

    const int d = d0 + tx;
    const float w0 = cw[d * 4 + 0], w1 = cw[d * 4 + 1];
    const float w2 = cw[d * 4 + 2], w3 = cw[d * 4 + 3];
    const float bb = cb[d];

    for (int ll = ty; ll < 32; ll += 8) {
        float acc = su[ll][tx] * w0 + su[ll + 1][tx] * w1
                  + su[ll + 2][tx] * w2 + su[ll + 3][tx] * w3 + bb;
        const float sv = acc / (1.f + __expf(-acc));
        const int m = b * SEQLEN + l0 + ll;
        uc[(size_t)m * DINNER + d] = sv;
        so[ll][tx] = sv;
    }
    __syncthreads();

    for (int dd = ty; dd < 32; dd += 8)
        uct[(size_t)(b * DINNER + d0 + dd) * SEQLEN + l0 + tx] = so[tx][dd];
}

// ---------------- dt_proj + softplus (transposed) ----------------
__global__ __launch_bounds__(256) void dtproj_kernel(
    const float* __restrict__ xdbl, const float* __restrict__ dtw,
    const float* __restrict__ dtb, float* __restrict__ deltat)
{
    __shared__ float sdt[32][17];
    __shared__ float sw[32][17];
    __shared__ float so[32][33];
    const int d0 = blockIdx.x * 32;
    const int m0 = blockIdx.y * 32;
    const int tid = threadIdx.x;

    {
        const int r = tid >> 4, c = tid & 15;
        sdt[r][c]      = xdbl[(size_t)(m0 + r) * 48 + c];
        sdt[r + 16][c] = xdbl[(size_t)(m0 + r + 16) * 48 + c];
        sw[r][c]       = dtw[(d0 + r) * 16 + c];
        sw[r + 16][c]  = dtw[(d0 + r + 16) * 16 + c];
    }
    __syncthreads();

    const int dloc = tid & 31;
    const float bias = dtb[d0 + dloc];
    for (int ll = tid >> 5; ll < 32; ll += 8) {
        float acc = bias;
#pragma unroll
        for (int k = 0; k < 16; k++) acc = fmaf(sdt[ll][k], sw[dloc][k], acc);
        so[ll][dloc] = fmaxf(acc, 0.f) + __logf(1.f + __expf(-fabsf(acc)));
    }
    __syncthreads();

    const int b  = m0 / SEQLEN;
    const int l0 = m0 % SEQLEN;
    for (int dd = tid >> 5; dd < 32; dd += 8)
        deltat[(size_t)(b * DINNER + d0 + dd) * SEQLEN + l0 + dloc] = so[dloc][dd];
}

// ---------------- selective scan: blocked-16 + register transpose-reduce ----
__global__ __launch_bounds__(256) void scan_kernel(
    const float* __restrict__ deltat, const float* __restrict__ uct,
    const float* __restrict__ xdbl, const float* __restrict__ Alog,
    float* __restrict__ yscant)
{
    const int warp = (blockIdx.x * blockDim.x + threadIdx.x) >> 5;
    const int lane = threadIdx.x & 31;
    const int half = lane >> 4;
    const int s    = lane & 15;
    const int ch   = warp * 2 + half;
    const int b    = ch >> 9;
    const int d    = ch & 511;

    const float A = -__expf(Alog[d * DSTATE + s]);
    float state = 0.f;

    const float4* dp4 = (const float4*)(deltat + (size_t)ch * SEQLEN);
    const float4* up4 = (const float4*)(uct    + (size_t)ch * SEQLEN);
    const float* xB   = xdbl + (size_t)b * SEQLEN * 48 + 16 + s;
    float* yout = yscant + (size_t)ch * SEQLEN;

    for (int l0 = 0; l0 < SEQLEN; l0 += 16) {
        float p[16];
        const int q0 = l0 >> 2;
#pragma unroll
        for (int blk = 0; blk < 4; blk++) {
            const float4 dt4 = __ldg(dp4 + q0 + blk);
            const float4 ut4 = __ldg(up4 + q0 + blk);
            const float dts[4] = {dt4.x, dt4.y, dt4.z, dt4.w};
            const float uts[4] = {ut4.x, ut4.y, ut4.z, ut4.w};
#pragma unroll
            for (int j = 0; j < 4; j++) {
                const float Bv = __ldg(xB);
                const float Cv = __ldg(xB + 16);
                xB += 48;
                const float dA = __expf(dts[j] * A);
                state = fmaf(state, dA, dts[j] * uts[j] * Bv);
                p[blk * 4 + j] = state * Cv;
            }
        }
        float q8[8];
#pragma unroll
        for (int j = 0; j < 8; j++) {
            const float send = (s & 8) ? p[j] : p[j + 8];
            const float r = __shfl_xor_sync(0xffffffffu, send, 8);
            q8[j] = ((s & 8) ? p[j + 8] : p[j]) + r;
        }
        float q4[4];
#pragma unroll
        for (int j = 0; j < 4; j++) {
            const float send = (s & 4) ? q8[j] : q8[j + 4];
            const float r = __shfl_xor_sync(0xffffffffu, send, 4);
            q4[j] = ((s & 4) ? q8[j + 4] : q8[j]) + r;
        }
        float q2[2];
#pragma unroll
        for (int j = 0; j < 2; j++) {
            const float send = (s & 2) ? q4[j] : q4[j + 2];
            const float r = __shfl_xor_sync(0xffffffffu, send, 2);
            q2[j] = ((s & 2) ? q4[j + 2] : q4[j]) + r;
        }
        {
            const float send = (s & 1) ? q2[0] : q2[1];
            const float r = __shfl_xor_sync(0xffffffffu, send, 1);
            yout[l0 + s] = ((s & 1) ? q2[1] : q2[0]) + r;
        }
    }
}

// ---------------- gate (+ bf16 hi/lo split of y) ----------------
__global__ __launch_bounds__(256) void gate_kernel(
    const float* __restrict__ yscant, const float* __restrict__ uc,
    const float* __restrict__ xz, const float* __restrict__ Dw,
    __nv_bfloat16* __restrict__ yh, __nv_bfloat16* __restrict__ yl)
{
    __shared__ float s[32][33];
    const int d0 = blockIdx.x * 32;
    const int l0 = blockIdx.y * 32;
    const int b  = blockIdx.z;
    const int tx = threadIdx.x & 31;
    const int ty = threadIdx.x >> 5;

    for (int dd = ty; dd < 32; dd += 8)
        s[dd][tx] = yscant[(size_t)(b * DINNER + d0 + dd) * SEQLEN + l0 + tx];
    __syncthreads();

    const int d = d0 + tx;
    const float Dv = Dw[d];
    for (int ll = ty; ll < 32; ll += 8) {
        const int m = b * SEQLEN + l0 + ll;
        const float ucv = uc[(size_t)m * DINNER + d];
        const float zv  = xz[(size_t)m * 1024 + DINNER + d];
        const float silu_z = zv / (1.f + __expf(-zv));
        const float v = (s[tx][ll] + Dv * ucv) * silu_z;
        const __nv_bfloat16 hv = __float2bfloat16(v);
        yh[(size_t)m * DINNER + d] = hv;
        yl[(size_t)m * DINNER + d] = __float2bfloat16(v - __bfloat162float(hv));
    }
}

// ---------------- residual + LayerNorm ----------------
__global__ __launch_bounds__(256) void ln_kernel(
    const float* __restrict__ outtmp, const float* __restrict__ x,
    const float* __restrict__ g, const float* __restrict__ beta,
    float* __restrict__ out)
{
    const int warp = threadIdx.x >> 5;
    const int lane = threadIdx.x & 31;
    const int row = blockIdx.x * 8 + warp;

    float h[8];
    float sum = 0.f, sq = 0.f;
#pragma unroll
    for (int i = 0; i < 8; i++) {
        const int c = lane + i * 32;
        const float v = outtmp[(size_t)row * 256 + c] + x[(size_t)row * 256 + c];
        h[i] = v; sum += v; sq = fmaf(v, v, sq);
    }
#pragma unroll
    for (int o = 16; o; o >>= 1) {
        sum += __shfl_xor_sync(0xffffffffu, sum, o);
        sq  += __shfl_xor_sync(0xffffffffu, sq,  o);
    }
    const float mu  = sum * (1.f / 256.f);
    const float var = sq * (1.f / 256.f) - mu * mu;
    const float inv = rsqrtf(var + 1e-5f);
#pragma unroll
    for (int i = 0; i < 8; i++) {
        const int c = lane + i * 32;
        out[(size_t)row * 256 + c] = (h[i] - mu) * inv * g[c] + beta[c];
    }
}

// ---------------------------------------------------------------------------
extern "C" void kernel_launch(void* const* d_in, const int* in_sizes, int n_in,
                              void* d_out, int out_size)
{
    const float* x       = (const float*)d_in[0];
    const float* in_w    = (const float*)d_in[1];
    const float* conv_w  = (const float*)d_in[2];
    const float* conv_b  = (const float*)d_in[3];
    const float* xproj_w = (const float*)d_in[4];
    const float* dt_w    = (const float*)d_in[5];
    const float* dt_b    = (const float*)d_in[6];
    const float* A_log   = (const float*)d_in[7];
    const float* Dw      = (const float*)d_in[8];
    const float* out_w   = (const float*)d_in[9];
    const float* ln_g    = (const float*)d_in[10];
    const float* ln_b    = (const float*)d_in[11];
    float* out = (float*)d_out;

    float* base = nullptr;
    cudaGetSymbolAddress((void**)&base, g_scratch);
    float* xz     = base + OFF_XZ;
    float* uc     = base + OFF_UC;
    float* uct    = base + OFF_UCT;
    float* xdbl   = base + OFF_XDBL;
    float* deltat = base + OFF_DELTAT;
    float* yscant = base + OFF_YSCANT;
    float* outtmp = base + OFF_OUTTMP;
    __nv_bfloat16* xh  = (__nv_bfloat16*)(base + OFF_XH);
    __nv_bfloat16* xl  = (__nv_bfloat16*)(base + OFF_XL);
    __nv_bfloat16* yh  = (__nv_bfloat16*)(base + OFF_YH);
    __nv_bfloat16* yl  = (__nv_bfloat16*)(base + OFF_YL);
    __nv_bfloat16* wih = (__nv_bfloat16*)(base + OFF_WIH);
    __nv_bfloat16* wil = (__nv_bfloat16*)(base + OFF_WIL);
    __nv_bfloat16* woh = (__nv_bfloat16*)(base + OFF_WOH);
    __nv_bfloat16* wol = (__nv_bfloat16*)(base + OFF_WOL);

    cudaFuncSetAttribute(gemm_tc3_kernel,
                         cudaFuncAttributeMaxDynamicSharedMemorySize,
                         GTC_SMEM_BYTES);

    split_kernel<<<(MROWS * DMODEL / 4 + 255) / 256, 256>>>(
        (const float4*)x, (uint2*)xh, (uint2*)xl, MROWS * DMODEL / 4);
    split_kernel<<<(1024 * DMODEL / 4 + 255) / 256, 256>>>(
        (const float4*)in_w, (uint2*)wih, (uint2*)wil, 1024 * DMODEL / 4);
    split_kernel<<<(DMODEL * DINNER / 4 + 255) / 256, 256>>>(
        (const float4*)out_w, (uint2*)woh, (uint2*)wol, DMODEL * DINNER / 4);

    gemm_tc3_kernel<<<dim3(1024 / 128, MROWS / 128), 256, GTC_SMEM_BYTES>>>(
        xh, xl, wih, wil, xz, MROWS, 1024, DMODEL);

    conv_silu_kernel<<<dim3(DINNER / 32, SEQLEN / 32, BATCH), 256>>>(
        xz, conv_w, conv_b, uc, uct);

    sgemm_kernel<<<dim3(1, MROWS / 128), 256>>>(uc, xproj_w, xdbl, MROWS, 48, 512);

    dtproj_kernel<<<dim3(DINNER / 32, MROWS / 32), 256>>>(xdbl, dt_w, dt_b, deltat);

    scan_kernel<<<NCH / 16, 256>>>(deltat, uct, xdbl, A_log, yscant);

    gate_kernel<<<dim3(DINNER / 32, SEQLEN / 32, BATCH), 256>>>(
        yscant, uc, xz, Dw, yh, yl);

    gemm_tc3_kernel<<<dim3(256 / 128, MROWS / 128), 256, GTC_SMEM_BYTES>>>(
        yh, yl, woh, wol, outtmp, MROWS, 256, DINNER);

    ln_kernel<<<MROWS / 8, 256>>>(outtmp, x, ln_g, ln_b, out);
}